// round 4
// baseline (speedup 1.0000x reference)
#include <cuda_runtime.h>
#include <cuda_bf16.h>
#include <math.h>

// Problem dims
#define BB 1024
#define TT 512
#define FF 64
#define HH 128
#define GG 384   // 3*H, gate order (r, z, n)
#define NB 7     // batch rows per block in recurrence (147*7 = 1029 >= 1024)

// Packed f32x2 FMA (Blackwell FFMA2 — only reachable via PTX)
#define FMA_F32X2(d, a, b, c) \
    asm("fma.rn.f32x2 %0, %1, %2, %3;" : "=l"(d) : "l"(a), "l"(b), "l"(c))

__device__ __forceinline__ void unpack2(unsigned long long p, float& lo, float& hi) {
    unsigned int l, h;
    asm("mov.b64 {%0, %1}, %2;" : "=r"(l), "=r"(h) : "l"(p));
    lo = __uint_as_float(l);
    hi = __uint_as_float(h);
}

// Scratch (allocation-free rule: __device__ globals)
__device__ float g_xg[(size_t)BB * TT * GG];  // [B*T, 3H] input-side pre-acts (includes b_ih)
__device__ float g_hT[BB * HH];               // final hidden state

// ---------------------------------------------------------------------------
// Kernel A: xg[bt, g] = dot(x[bt, :], W_ih[g, :]) + b_ih[g]
// One thread per gate column g (384 threads), 64 bt-rows per block.
// W_ih row in packed f32x2 registers; x tile in smem (broadcast 128-bit reads).
// ---------------------------------------------------------------------------
#define A_TILE 64

__global__ __launch_bounds__(GG) void xg_kernel(
    const float* __restrict__ x,
    const float* __restrict__ W_ih,
    const float* __restrict__ b_ih)
{
    __shared__ __align__(16) float xs[A_TILE][FF];   // 16 KB

    const int g = threadIdx.x;                        // 0..383
    const size_t bt0 = (size_t)blockIdx.x * A_TILE;

    // Cooperative coalesced load of the x tile
    for (int i = threadIdx.x; i < A_TILE * FF; i += GG)
        ((float*)xs)[i] = x[bt0 * FF + i];

    // Per-thread weights, packed 2-wide (row offset g*64*4B = 8B-aligned)
    unsigned long long w2[FF / 2];
    {
        const unsigned long long* wp = (const unsigned long long*)(W_ih + (size_t)g * FF);
#pragma unroll
        for (int k = 0; k < FF / 2; k++) w2[k] = wp[k];
    }
    const float bias = b_ih[g];

    __syncthreads();

    for (int r = 0; r < A_TILE; r++) {
        unsigned long long a0 = 0ull, a1 = 0ull;
        const ulonglong2* xr = (const ulonglong2*)xs[r];  // broadcast LDS.128
#pragma unroll
        for (int k = 0; k < FF / 4; k++) {
            ulonglong2 v = xr[k];
            FMA_F32X2(a0, v.x, w2[2 * k + 0], a0);
            FMA_F32X2(a1, v.y, w2[2 * k + 1], a1);
        }
        float s0, s1, s2, s3;
        unpack2(a0, s0, s1);
        unpack2(a1, s2, s3);
        g_xg[(bt0 + r) * GG + g] = (s0 + s1) + (s2 + s3) + bias;
    }
}

// ---------------------------------------------------------------------------
// Kernel B: sequential GRU over T. Each block owns NB batch rows; no
// cross-block dependency. W_hh[g,:] lives in 64 packed-f32x2 registers per
// thread. h lives in smem. Two __syncthreads per step.
// ---------------------------------------------------------------------------
__global__ __launch_bounds__(GG, 1) void gru_kernel(
    const float* __restrict__ W_hh,
    const float* __restrict__ b_hh)
{
    __shared__ __align__(16) float h_s[NB][HH];      // current hidden, 3.5 KB
    __shared__ float hg_s[NB][GG];                   // gate pre-acts, 10.5 KB
    __shared__ float xn_s[NB][HH];                   // x-side n pre-act, 3.5 KB

    const int g = threadIdx.x;                       // gate column 0..383
    const int row0 = blockIdx.x * NB;
    const int gj = g & (HH - 1);
    const int gsel = g >> 7;                         // 0=r, 1=z, 2=n

    // One-time weight load into packed registers (row offset 512B-aligned)
    unsigned long long w2[HH / 2];
    {
        const unsigned long long* wp = (const unsigned long long*)(W_hh + (size_t)g * HH);
#pragma unroll
        for (int k = 0; k < HH / 2; k++) w2[k] = wp[k];
    }
    const float bias = b_hh[g];

    // h0 = 0
    for (int i = threadIdx.x; i < NB * HH; i += GG)
        ((float*)h_s)[i] = 0.f;
    __syncthreads();

    for (int t = 0; t < TT; t++) {
        // Prefetch this step's xg values (latency hidden behind FMA loop)
        float xv[NB];
#pragma unroll
        for (int r = 0; r < NB; r++) {
            int row = min(row0 + r, BB - 1);          // clamp padded rows
            xv[r] = g_xg[((size_t)row * TT + t) * GG + g];
        }

        // hg[r][g] = h[r,:] . W_hh[g,:]  (packed f32x2 FMAs)
#pragma unroll
        for (int r = 0; r < NB; r++) {
            unsigned long long a0 = 0ull, a1 = 0ull;
            const ulonglong2* hp = (const ulonglong2*)h_s[r];  // broadcast LDS.128
#pragma unroll
            for (int k = 0; k < HH / 4; k++) {
                ulonglong2 v = hp[k];
                FMA_F32X2(a0, v.x, w2[2 * k + 0], a0);
                FMA_F32X2(a1, v.y, w2[2 * k + 1], a1);
            }
            float s0, s1, s2, s3;
            unpack2(a0, s0, s1);
            unpack2(a1, s2, s3);
            float acc = (s0 + s1) + (s2 + s3) + bias;
            if (gsel < 2) {
                hg_s[r][g] = acc + xv[r];             // full pre-act for r, z
            } else {
                hg_s[r][g] = acc;                     // h-side only for n
                xn_s[r][gj] = xv[r];                  // x-side of n
            }
        }
        __syncthreads();

        // Gate math: 896 (row, j) pairs over 384 threads
#pragma unroll
        for (int p = 0; p < 3; p++) {
            int idx = g + p * GG;
            if (idx < NB * HH) {
                int r = idx >> 7;
                int j = idx & (HH - 1);
                float rr = 1.f / (1.f + __expf(-hg_s[r][j]));
                float zz = 1.f / (1.f + __expf(-hg_s[r][HH + j]));
                float nn = tanhf(xn_s[r][j] + rr * hg_s[r][2 * HH + j]);
                h_s[r][j] = (1.f - zz) * nn + zz * h_s[r][j];  // unique owner
            }
        }
        __syncthreads();
    }

    // Emit final hidden state
    for (int i = threadIdx.x; i < NB * HH; i += GG) {
        int r = i >> 7;
        int row = row0 + r;
        if (row < BB) g_hT[row * HH + (i & (HH - 1))] = ((float*)h_s)[i];
    }
}

// ---------------------------------------------------------------------------
// Kernel C: out[b] = W2 . relu(hT[b] @ W1^T + b1) + b2. One warp per row.
// ---------------------------------------------------------------------------
__global__ void head_kernel(
    const float* __restrict__ W1,
    const float* __restrict__ b1,
    const float* __restrict__ W2,
    const float* __restrict__ b2,
    float* __restrict__ out)
{
    const int b = blockIdx.x;
    const int j = threadIdx.x;                       // 0..31
    const float* h = g_hT + b * HH;

    float acc = 0.f;
#pragma unroll
    for (int k = 0; k < HH; k++)
        acc = fmaf(h[k], W1[j * HH + k], acc);

    float hid = fmaxf(acc + b1[j], 0.f);
    float v = hid * W2[j];
#pragma unroll
    for (int off = 16; off; off >>= 1)
        v += __shfl_xor_sync(0xffffffffu, v, off);
    if (j == 0) out[b] = v + b2[0];
}

// ---------------------------------------------------------------------------
extern "C" void kernel_launch(void* const* d_in, const int* in_sizes, int n_in,
                              void* d_out, int out_size)
{
    const float* x    = (const float*)d_in[0];
    const float* W_ih = (const float*)d_in[1];
    const float* W_hh = (const float*)d_in[2];
    const float* b_ih = (const float*)d_in[3];
    const float* b_hh = (const float*)d_in[4];
    const float* W1   = (const float*)d_in[5];
    const float* b1   = (const float*)d_in[6];
    const float* W2   = (const float*)d_in[7];
    const float* b2   = (const float*)d_in[8];
    float* out        = (float*)d_out;

    // A: input-side pre-activations for all timesteps
    xg_kernel<<<(BB * TT) / A_TILE, GG>>>(x, W_ih, b_ih);

    // B: sequential recurrence, one wave of persistent blocks
    gru_kernel<<<(BB + NB - 1) / NB, GG>>>(W_hh, b_hh);

    // C: MLP head
    head_kernel<<<BB, 32>>>(W1, b1, W2, b2, out);
}

// round 5
// speedup vs baseline: 1.3206x; 1.3206x over previous
#include <cuda_runtime.h>
#include <cuda_bf16.h>
#include <math.h>

// Problem dims
#define BB 1024
#define TT 512
#define FF 64
#define HH 128
#define GG 384   // 3*H, gate order (r, z, n)
#define NB 7     // batch rows per block in recurrence (147*7 = 1029 >= 1024)

// Packed f32x2 FMA (PTX; may lower to FFMA2 or 2xFFMA depending on arch)
#define FMA_F32X2(d, a, b, c) \
    asm("fma.rn.f32x2 %0, %1, %2, %3;" : "=l"(d) : "l"(a), "l"(b), "l"(c))

__device__ __forceinline__ void unpack2(unsigned long long p, float& lo, float& hi) {
    unsigned int l, h;
    asm("mov.b64 {%0, %1}, %2;" : "=r"(l), "=r"(h) : "l"(p));
    lo = __uint_as_float(l);
    hi = __uint_as_float(h);
}

__device__ __forceinline__ float sigmoid_fast(float x) {
    return __fdividef(1.f, 1.f + __expf(-x));
}
__device__ __forceinline__ float tanh_fast(float x) {
    // 1 - 2/(e^{2x}+1): exact saturation at +/-inf, no NaN paths
    return 1.f - __fdividef(2.f, __expf(2.f * x) + 1.f);
}

// cp.async helpers (16B variant)
__device__ __forceinline__ void cp_async16(unsigned int smem_addr, const void* gptr) {
    asm volatile("cp.async.cg.shared.global [%0], [%1], 16;" :: "r"(smem_addr), "l"(gptr));
}
__device__ __forceinline__ void cp_commit() {
    asm volatile("cp.async.commit_group;");
}
__device__ __forceinline__ void cp_wait_all() {
    asm volatile("cp.async.wait_group 0;" ::: "memory");
}

// Scratch (allocation-free rule: __device__ globals)
__device__ float g_xg[(size_t)BB * TT * GG];  // [B*T, 3H] input-side pre-acts (includes b_ih)
__device__ float g_hT[BB * HH];               // final hidden state

// ---------------------------------------------------------------------------
// Kernel A: xg[bt, g] = dot(x[bt, :], W_ih[g, :]) + b_ih[g]
// 768 threads: pair (g, kh) — thread owns K-half kh of gate column g.
// 32 weights/thread in packed regs (~50 regs -> 24 warps/SM). Shfl-combine.
// Split smem halves padded by 16B so the two per-instruction address groups
// hit disjoint banks.
// ---------------------------------------------------------------------------
#define A_TILE 64
#define A_THREADS 768
#define A_HALF (A_TILE * 32)          // floats per half

__global__ __launch_bounds__(A_THREADS) void xg_kernel(
    const float* __restrict__ x,
    const float* __restrict__ W_ih,
    const float* __restrict__ b_ih)
{
    __shared__ __align__(16) float xs[2 * A_HALF + 4];  // +4 floats pad between halves

    const int tid = threadIdx.x;
    const int g = tid >> 1;                 // 0..383
    const int kh = tid & 1;                 // K-half
    const size_t bt0 = (size_t)blockIdx.x * A_TILE;

    // Cooperative coalesced load of the x tile, split into two padded halves.
    // 1024 float4 chunks; chunk i: row r=i/16, quarter cq=i%16 (8 per half).
    for (int i = tid; i < A_TILE * FF / 4; i += A_THREADS) {
        int r = i >> 4, cq = i & 15;
        int half = cq >> 3, w = cq & 7;
        float4 v = ((const float4*)(x + bt0 * FF))[i];
        ((float4*)xs)[half * (A_HALF / 4 + 1) + r * 8 + w] = v;
    }

    // Per-thread weights: 32 floats = 16 packed
    unsigned long long w2[16];
    {
        const unsigned long long* wp =
            (const unsigned long long*)(W_ih + (size_t)g * FF + kh * 32);
#pragma unroll
        for (int k = 0; k < 16; k++) w2[k] = wp[k];
    }
    const float bias = b_ih[g];

    __syncthreads();

    const float* my_half = xs + kh * (A_HALF + 4);
    for (int r = 0; r < A_TILE; r++) {
        unsigned long long a0 = 0ull, a1 = 0ull;
        const ulonglong2* xr = (const ulonglong2*)(my_half + r * 32);
#pragma unroll
        for (int k = 0; k < 8; k++) {
            ulonglong2 v = xr[k];
            FMA_F32X2(a0, v.x, w2[2 * k + 0], a0);
            FMA_F32X2(a1, v.y, w2[2 * k + 1], a1);
        }
        float s0, s1, s2, s3;
        unpack2(a0, s0, s1);
        unpack2(a1, s2, s3);
        float s = (s0 + s1) + (s2 + s3);
        s += __shfl_xor_sync(0xffffffffu, s, 1);   // combine K-halves (same warp)
        if (kh == 0) g_xg[(bt0 + r) * GG + g] = s + bias;
    }
}

// ---------------------------------------------------------------------------
// Kernel B: sequential GRU over T. 384 threads; W_hh[g,:] in 128 regs;
// serial r-loop (no unroll) keeps total regs ~150 -> no spill.
// xg staged through a cp.async double-buffered smem ring (latency hidden).
// ---------------------------------------------------------------------------
__global__ __launch_bounds__(GG, 1) void gru_kernel(
    const float* __restrict__ W_hh,
    const float* __restrict__ b_hh)
{
    __shared__ __align__(16) float h_s[NB][HH];        // 3.5 KB
    __shared__ float hg_s[NB][GG];                     // 10.5 KB
    __shared__ __align__(16) float xg_s[2][NB][GG];    // 21 KB double buffer

    const int g = threadIdx.x;                         // gate column 0..383
    const int row0 = blockIdx.x * NB;
    const int gsel = g >> 7;                           // 0=r, 1=z, 2=n

    // One-time packed weight load (row offset 512B-aligned)
    unsigned long long w2[HH / 2];
    {
        const unsigned long long* wp =
            (const unsigned long long*)(W_hh + (size_t)g * HH);
#pragma unroll
        for (int k = 0; k < HH / 2; k++) w2[k] = wp[k];
    }
    const float bias = b_hh[g];

    const unsigned int xg_s_addr = (unsigned int)__cvta_generic_to_shared(&xg_s[0][0][0]);

    // Async stage of step t's xg into buffer buf: NB*GG*4B = 672 x 16B chunks
    auto stage_xg = [&](int t, int buf) {
        if (t < TT) {
            for (int c = g; c < NB * GG / 4; c += GG) {
                int r = c / (GG / 4);
                int off = c % (GG / 4);                 // 16B chunk within row
                int row = min(row0 + r, BB - 1);
                const char* src =
                    (const char*)(g_xg + ((size_t)row * TT + t) * GG) + off * 16;
                cp_async16(xg_s_addr + (unsigned)(buf * NB * GG + r * GG) * 4u + off * 16u, src);
            }
        }
        cp_commit();
    };

    // h0 = 0; preload t=0
    for (int i = threadIdx.x; i < NB * HH; i += GG)
        ((float*)h_s)[i] = 0.f;
    stage_xg(0, 0);
    cp_wait_all();
    __syncthreads();

    for (int t = 0; t < TT; t++) {
        const int buf = t & 1;

        // Kick off next step's staging (latency hidden across this whole step)
        stage_xg(t + 1, buf ^ 1);

        // FMA phase: hg[r][g] = h[r,:] . W_hh[g,:]   (serial rows, 4 chains)
#pragma unroll 1
        for (int r = 0; r < NB; r++) {
            unsigned long long a0 = 0ull, a1 = 0ull, a2 = 0ull, a3 = 0ull;
            const ulonglong2* hp = (const ulonglong2*)h_s[r];  // broadcast LDS.128
#pragma unroll
            for (int k = 0; k < HH / 8; k++) {                 // 16 iters
                ulonglong2 v0 = hp[2 * k + 0];
                ulonglong2 v1 = hp[2 * k + 1];
                FMA_F32X2(a0, v0.x, w2[4 * k + 0], a0);
                FMA_F32X2(a1, v0.y, w2[4 * k + 1], a1);
                FMA_F32X2(a2, v1.x, w2[4 * k + 2], a2);
                FMA_F32X2(a3, v1.y, w2[4 * k + 3], a3);
            }
            float s0, s1, s2, s3, s4, s5, s6, s7;
            unpack2(a0, s0, s1);
            unpack2(a1, s2, s3);
            unpack2(a2, s4, s5);
            unpack2(a3, s6, s7);
            float acc = ((s0 + s1) + (s2 + s3)) + ((s4 + s5) + (s6 + s7)) + bias;
            if (gsel < 2) acc += xg_s[buf][r][g];      // fold x-side for r, z
            hg_s[r][g] = acc;
        }
        __syncthreads();

        // Gate phase: 896 (row, j) pairs over 384 threads
#pragma unroll
        for (int p = 0; p < 3; p++) {
            int idx = g + p * GG;
            if (idx < NB * HH) {
                int r = idx >> 7;
                int j = idx & (HH - 1);
                float rr = sigmoid_fast(hg_s[r][j]);
                float zz = sigmoid_fast(hg_s[r][HH + j]);
                float nn = tanh_fast(xg_s[buf][r][2 * HH + j] + rr * hg_s[r][2 * HH + j]);
                h_s[r][j] = (1.f - zz) * nn + zz * h_s[r][j];   // unique owner
            }
        }

        cp_wait_all();        // next buffer filled (per-thread) ...
        __syncthreads();      // ... and visible block-wide
    }

    // Emit final hidden state
    for (int i = threadIdx.x; i < NB * HH; i += GG) {
        int r = i >> 7;
        int row = row0 + r;
        if (row < BB) g_hT[row * HH + (i & (HH - 1))] = ((float*)h_s)[i];
    }
}

// ---------------------------------------------------------------------------
// Kernel C: out[b] = W2 . relu(hT[b] @ W1^T + b1) + b2. One warp per row.
// ---------------------------------------------------------------------------
__global__ void head_kernel(
    const float* __restrict__ W1,
    const float* __restrict__ b1,
    const float* __restrict__ W2,
    const float* __restrict__ b2,
    float* __restrict__ out)
{
    const int b = blockIdx.x;
    const int j = threadIdx.x;                       // 0..31
    const float* h = g_hT + b * HH;

    float acc = 0.f;
#pragma unroll
    for (int k = 0; k < HH; k++)
        acc = fmaf(h[k], W1[j * HH + k], acc);

    float hid = fmaxf(acc + b1[j], 0.f);
    float v = hid * W2[j];
#pragma unroll
    for (int off = 16; off; off >>= 1)
        v += __shfl_xor_sync(0xffffffffu, v, off);
    if (j == 0) out[b] = v + b2[0];
}

// ---------------------------------------------------------------------------
extern "C" void kernel_launch(void* const* d_in, const int* in_sizes, int n_in,
                              void* d_out, int out_size)
{
    const float* x    = (const float*)d_in[0];
    const float* W_ih = (const float*)d_in[1];
    const float* W_hh = (const float*)d_in[2];
    const float* b_ih = (const float*)d_in[3];
    const float* b_hh = (const float*)d_in[4];
    const float* W1   = (const float*)d_in[5];
    const float* b1   = (const float*)d_in[6];
    const float* W2   = (const float*)d_in[7];
    const float* b2   = (const float*)d_in[8];
    float* out        = (float*)d_out;

    // A: input-side pre-activations for all timesteps
    xg_kernel<<<(BB * TT) / A_TILE, A_THREADS>>>(x, W_ih, b_ih);

    // B: sequential recurrence, one wave of persistent blocks
    gru_kernel<<<(BB + NB - 1) / NB, GG>>>(W_hh, b_hh);

    // C: MLP head
    head_kernel<<<BB, 32>>>(W1, b1, W2, b2, out);
}

// round 7
// speedup vs baseline: 1.3737x; 1.0401x over previous
#include <cuda_runtime.h>
#include <cuda_bf16.h>
#include <math.h>

// Problem dims
#define BB 1024
#define TT 512
#define FF 64
#define HH 128
#define GG 384   // 3*H, gate order (r, z, n)
#define NB 7     // batch rows per block in recurrence (147*7 = 1029 >= 1024)

// Packed f32x2 FMA (PTX; FFMA2 on Blackwell)
#define FMA_F32X2(d, a, b, c) \
    asm("fma.rn.f32x2 %0, %1, %2, %3;" : "=l"(d) : "l"(a), "l"(b), "l"(c))

__device__ __forceinline__ void unpack2(unsigned long long p, float& lo, float& hi) {
    unsigned int l, h;
    asm("mov.b64 {%0, %1}, %2;" : "=r"(l), "=r"(h) : "l"(p));
    lo = __uint_as_float(l);
    hi = __uint_as_float(h);
}

__device__ __forceinline__ float sigmoid_fast(float x) {
    return __fdividef(1.f, 1.f + __expf(-x));
}
__device__ __forceinline__ float tanh_fast(float x) {
    return 1.f - __fdividef(2.f, __expf(2.f * x) + 1.f);
}

// cp.async helpers (16B)
__device__ __forceinline__ void cp_async16(unsigned int smem_addr, const void* gptr) {
    asm volatile("cp.async.cg.shared.global [%0], [%1], 16;" :: "r"(smem_addr), "l"(gptr));
}
__device__ __forceinline__ void cp_commit() {
    asm volatile("cp.async.commit_group;");
}
__device__ __forceinline__ void cp_wait_all() {
    asm volatile("cp.async.wait_group 0;" ::: "memory");
}

// Scratch (allocation-free rule: __device__ globals)
__device__ float g_xg[(size_t)BB * TT * GG];  // [B*T, 3H] input-side pre-acts (includes b_ih)
__device__ float g_hT[BB * HH];               // final hidden state

// ---------------------------------------------------------------------------
// Kernel A: xg[bt, g] = dot(x[bt, :], W_ih[g, :]) + b_ih[g]
// 768 threads: (g, kh) pairs; 2-row inner unroll for 4 independent FMA chains.
// ---------------------------------------------------------------------------
#define A_TILE 64
#define A_THREADS 768
#define A_HALF (A_TILE * 32)          // floats per K-half

__global__ __launch_bounds__(A_THREADS) void xg_kernel(
    const float* __restrict__ x,
    const float* __restrict__ W_ih,
    const float* __restrict__ b_ih)
{
    __shared__ __align__(16) float xs[2 * A_HALF + 4];  // pad between halves

    const int tid = threadIdx.x;
    const int g = tid >> 1;                 // 0..383
    const int kh = tid & 1;                 // K-half
    const size_t bt0 = (size_t)blockIdx.x * A_TILE;

    // Cooperative coalesced load of the x tile, split into two padded halves
    for (int i = tid; i < A_TILE * FF / 4; i += A_THREADS) {
        int r = i >> 4, cq = i & 15;
        int half = cq >> 3, w = cq & 7;
        float4 v = ((const float4*)(x + bt0 * FF))[i];
        ((float4*)xs)[half * (A_HALF / 4 + 1) + r * 8 + w] = v;
    }

    // Per-thread weights: 32 floats = 16 packed
    unsigned long long w2[16];
    {
        const unsigned long long* wp =
            (const unsigned long long*)(W_ih + (size_t)g * FF + kh * 32);
#pragma unroll
        for (int k = 0; k < 16; k++) w2[k] = wp[k];
    }
    const float bias = b_ih[g];

    __syncthreads();

    const float* my_half = xs + kh * (A_HALF + 4);
    for (int r = 0; r < A_TILE; r += 2) {
        unsigned long long a0 = 0ull, a1 = 0ull, b0 = 0ull, b1 = 0ull;
        const ulonglong2* xr0 = (const ulonglong2*)(my_half + r * 32);
        const ulonglong2* xr1 = (const ulonglong2*)(my_half + (r + 1) * 32);
#pragma unroll
        for (int k = 0; k < 8; k++) {
            ulonglong2 v0 = xr0[k];
            ulonglong2 v1 = xr1[k];
            FMA_F32X2(a0, v0.x, w2[2 * k + 0], a0);
            FMA_F32X2(a1, v0.y, w2[2 * k + 1], a1);
            FMA_F32X2(b0, v1.x, w2[2 * k + 0], b0);
            FMA_F32X2(b1, v1.y, w2[2 * k + 1], b1);
        }
        float s0, s1, s2, s3, t0, t1, t2, t3;
        unpack2(a0, s0, s1); unpack2(a1, s2, s3);
        unpack2(b0, t0, t1); unpack2(b1, t2, t3);
        float sa = (s0 + s1) + (s2 + s3);
        float sb = (t0 + t1) + (t2 + t3);
        sa += __shfl_xor_sync(0xffffffffu, sa, 1);   // combine K-halves
        sb += __shfl_xor_sync(0xffffffffu, sb, 1);
        if (kh == 0) {
            g_xg[(bt0 + r) * GG + g] = sa + bias;
            g_xg[(bt0 + r + 1) * GG + g] = sb + bias;
        }
    }
}

// ---------------------------------------------------------------------------
// Kernel B: sequential GRU over T. 768 threads, warp-uniform K-split:
// threads [0,384) own h[0:64], threads [384,768) own h[64:128].
// 64 weight floats per thread in 32 packed regs (~80 regs total -> no spill,
// 24 warps/SM). Partials combined in the gate phase (no extra syncs).
// xg staged via cp.async double buffer.
// ---------------------------------------------------------------------------
#define B_THREADS (2 * GG)   // 768

__global__ __launch_bounds__(B_THREADS, 1) void gru_kernel(
    const float* __restrict__ W_hh,
    const float* __restrict__ b_hh)
{
    __shared__ __align__(16) float h_s[NB][HH];        // 3.5 KB
    __shared__ float hg_p[2][NB][GG];                  // 21 KB partials
    __shared__ __align__(16) float xg_s[2][NB][GG];    // 21 KB double buffer

    const int tid = threadIdx.x;
    const int kh = tid / GG;                           // K-half (warp-uniform)
    const int g = tid - kh * GG;                       // gate column 0..383
    const int row0 = blockIdx.x * NB;

    // One-time packed weight load: 64 floats = 32 ullong (offset 256B-aligned)
    unsigned long long w2[32];
    {
        const unsigned long long* wp =
            (const unsigned long long*)(W_hh + (size_t)g * HH + kh * 64);
#pragma unroll
        for (int k = 0; k < 32; k++) w2[k] = wp[k];
    }
    const float bias = (kh == 0) ? b_hh[g] : 0.f;

    const unsigned int xg_s_addr = (unsigned int)__cvta_generic_to_shared(&xg_s[0][0][0]);

    // Async stage of step t's xg: NB*GG*4B = 672 x 16B chunks
    auto stage_xg = [&](int t, int buf) {
        if (t < TT) {
            for (int c = tid; c < NB * GG / 4; c += B_THREADS) {
                int r = c / (GG / 4);
                int off = c % (GG / 4);
                int row = min(row0 + r, BB - 1);
                const char* src =
                    (const char*)(g_xg + ((size_t)row * TT + t) * GG) + off * 16;
                cp_async16(xg_s_addr + (unsigned)(buf * NB * GG + r * GG) * 4u + off * 16u, src);
            }
        }
        cp_commit();
    };

    // h0 = 0; preload t=0
    for (int i = tid; i < NB * HH; i += B_THREADS)
        ((float*)h_s)[i] = 0.f;
    stage_xg(0, 0);
    cp_wait_all();
    __syncthreads();

    const float* h_base = &h_s[0][0] + kh * 64;

    for (int t = 0; t < TT; t++) {
        const int buf = t & 1;

        // Kick off next step's staging (hidden behind this step's compute)
        stage_xg(t + 1, buf ^ 1);

        // FMA phase: partial[kh][r][g] = h[r, kh*64 : kh*64+64] . w2
#pragma unroll 1
        for (int r = 0; r < NB; r++) {
            unsigned long long a0 = 0ull, a1 = 0ull;
            const ulonglong2* hp = (const ulonglong2*)(h_base + r * HH);  // broadcast
#pragma unroll
            for (int k = 0; k < 16; k++) {
                ulonglong2 v = hp[k];
                FMA_F32X2(a0, v.x, w2[2 * k + 0], a0);
                FMA_F32X2(a1, v.y, w2[2 * k + 1], a1);
            }
            float s0, s1, s2, s3;
            unpack2(a0, s0, s1);
            unpack2(a1, s2, s3);
            hg_p[kh][r][g] = (s0 + s1) + (s2 + s3) + bias;
        }
        __syncthreads();

        // Gate phase: 896 (row, j) pairs over 768 threads; combine partials here
#pragma unroll
        for (int p = 0; p < 2; p++) {
            int idx = tid + p * B_THREADS;
            if (idx < NB * HH) {
                int r = idx >> 7;
                int j = idx & (HH - 1);
                float pr = hg_p[0][r][j]        + hg_p[1][r][j];
                float pz = hg_p[0][r][HH + j]   + hg_p[1][r][HH + j];
                float pn = hg_p[0][r][2*HH + j] + hg_p[1][r][2*HH + j];
                float rr = sigmoid_fast(pr + xg_s[buf][r][j]);
                float zz = sigmoid_fast(pz + xg_s[buf][r][HH + j]);
                float nn = tanh_fast(xg_s[buf][r][2*HH + j] + rr * pn);
                h_s[r][j] = (1.f - zz) * nn + zz * h_s[r][j];   // unique owner
            }
        }

        cp_wait_all();        // next buffer filled (per-thread) ...
        __syncthreads();      // ... and visible block-wide
    }

    // Emit final hidden state
    for (int i = tid; i < NB * HH; i += B_THREADS) {
        int r = i >> 7;
        int row = row0 + r;
        if (row < BB) g_hT[row * HH + (i & (HH - 1))] = ((float*)h_s)[i];
    }
}

// ---------------------------------------------------------------------------
// Kernel C: out[b] = W2 . relu(hT[b] @ W1^T + b1) + b2. One warp per row.
// ---------------------------------------------------------------------------
__global__ void head_kernel(
    const float* __restrict__ W1,
    const float* __restrict__ b1,
    const float* __restrict__ W2,
    const float* __restrict__ b2,
    float* __restrict__ out)
{
    const int b = blockIdx.x;
    const int j = threadIdx.x;                       // 0..31
    const float* h = g_hT + b * HH;

    float acc = 0.f;
#pragma unroll
    for (int k = 0; k < HH; k++)
        acc = fmaf(h[k], W1[j * HH + k], acc);

    float hid = fmaxf(acc + b1[j], 0.f);
    float v = hid * W2[j];
#pragma unroll
    for (int off = 16; off; off >>= 1)
        v += __shfl_xor_sync(0xffffffffu, v, off);
    if (j == 0) out[b] = v + b2[0];
}

// ---------------------------------------------------------------------------
extern "C" void kernel_launch(void* const* d_in, const int* in_sizes, int n_in,
                              void* d_out, int out_size)
{
    const float* x    = (const float*)d_in[0];
    const float* W_ih = (const float*)d_in[1];
    const float* W_hh = (const float*)d_in[2];
    const float* b_ih = (const float*)d_in[3];
    const float* b_hh = (const float*)d_in[4];
    const float* W1   = (const float*)d_in[5];
    const float* b1   = (const float*)d_in[6];
    const float* W2   = (const float*)d_in[7];
    const float* b2   = (const float*)d_in[8];
    float* out        = (float*)d_out;

    xg_kernel<<<(BB * TT) / A_TILE, A_THREADS>>>(x, W_ih, b_ih);
    gru_kernel<<<(BB + NB - 1) / NB, B_THREADS>>>(W_hh, b_hh);
    head_kernel<<<BB, 32>>>(W1, b1, W2, b2, out);
}

// round 9
// speedup vs baseline: 1.8957x; 1.3800x over previous
#include <cuda_runtime.h>
#include <cuda_bf16.h>
#include <math.h>

// Problem dims
#define BB 1024
#define TT 512
#define FF 64
#define HH 128
#define GG 384   // 3*H, gate order (r, z, n)

// Packed f32x2 FMA (harmless 2xFFMA on sm_100a)
#define FMA_F32X2(d, a, b, c) \
    asm("fma.rn.f32x2 %0, %1, %2, %3;" : "=l"(d) : "l"(a), "l"(b), "l"(c))

__device__ __forceinline__ void unpack2(unsigned long long p, float& lo, float& hi) {
    unsigned int l, h;
    asm("mov.b64 {%0, %1}, %2;" : "=r"(l), "=r"(h) : "l"(p));
    lo = __uint_as_float(l);
    hi = __uint_as_float(h);
}

__device__ __forceinline__ float sigmoid_fast(float x) {
    return __fdividef(1.f, 1.f + __expf(-x));
}
__device__ __forceinline__ float tanh_fast(float x) {
    return 1.f - __fdividef(2.f, __expf(2.f * x) + 1.f);
}

// cp.async helpers (16B)
__device__ __forceinline__ void cp_async16(unsigned int smem_addr, const void* gptr) {
    asm volatile("cp.async.cg.shared.global [%0], [%1], 16;" :: "r"(smem_addr), "l"(gptr));
}
__device__ __forceinline__ void cp_commit() {
    asm volatile("cp.async.commit_group;");
}
__device__ __forceinline__ void cp_wait_all() {
    asm volatile("cp.async.wait_group 0;" ::: "memory");
}

// bf16 mma m16n8k16 row.col, f32 accumulate
__device__ __forceinline__ void mma_bf16(float* c, const unsigned* a, const unsigned* b) {
    asm volatile(
        "mma.sync.aligned.m16n8k16.row.col.f32.bf16.bf16.f32 "
        "{%0,%1,%2,%3}, {%4,%5,%6,%7}, {%8,%9}, {%0,%1,%2,%3};"
        : "+f"(c[0]), "+f"(c[1]), "+f"(c[2]), "+f"(c[3])
        : "r"(a[0]), "r"(a[1]), "r"(a[2]), "r"(a[3]), "r"(b[0]), "r"(b[1]));
}

__device__ __forceinline__ unsigned pack_bf16(float f0, float f1) {
    unsigned short u0 = __bfloat16_as_ushort(__float2bfloat16(f0));
    unsigned short u1 = __bfloat16_as_ushort(__float2bfloat16(f1));
    return (unsigned)u0 | ((unsigned)u1 << 16);
}

// Scratch (allocation-free rule: __device__ globals)
__device__ float g_xg[(size_t)BB * TT * GG];  // [B*T, 3H] input-side pre-acts (includes b_ih)
__device__ float g_hT[BB * HH];               // final hidden state

// ---------------------------------------------------------------------------
// Kernel A: xg[bt, g] = dot(x[bt, :], W_ih[g, :]) + b_ih[g]
// Persistent: 1024 blocks x 8 tiles, cp.async double-buffered tile staging.
// 768 threads: (g, kh) pairs; 2-row unroll for 4 independent FMA chains.
// ---------------------------------------------------------------------------
#define A_TILE 64
#define A_THREADS 768
#define A_HALF (A_TILE * 32)          // floats per K-half
#define A_TPB 8                        // tiles per block
#define A_BLOCKS ((BB * TT) / A_TILE / A_TPB)   // 1024
#define A_BUFSZ (2 * A_HALF + 8)       // floats per buffer (two padded halves)

__global__ __launch_bounds__(A_THREADS) void xg_kernel(
    const float* __restrict__ x,
    const float* __restrict__ W_ih,
    const float* __restrict__ b_ih)
{
    __shared__ __align__(16) float xs[2][A_BUFSZ];

    const int tid = threadIdx.x;
    const int g = tid >> 1;                 // 0..383
    const int kh = tid & 1;                 // K-half

    // Per-thread weights: 32 floats = 16 packed
    unsigned long long w2[16];
    {
        const unsigned long long* wp =
            (const unsigned long long*)(W_ih + (size_t)g * FF + kh * 32);
#pragma unroll
        for (int k = 0; k < 16; k++) w2[k] = wp[k];
    }
    const float bias = b_ih[g];

    const unsigned xs_base = (unsigned)__cvta_generic_to_shared(&xs[0][0]);

    // Stage one 64x64 x-tile into split padded halves via cp.async
    auto stage = [&](int tile, int buf) {
        const char* src = (const char*)(x + (size_t)tile * A_TILE * FF);
        for (int i = tid; i < A_TILE * FF / 4; i += A_THREADS) {
            int r = i >> 4, cq = i & 15;
            int half = cq >> 3, w = cq & 7;
            unsigned dst = xs_base + (unsigned)(buf * A_BUFSZ) * 4u
                         + (unsigned)(half * (A_HALF / 4 + 1) + r * 8 + w) * 16u;
            cp_async16(dst, src + (size_t)i * 16);
        }
        cp_commit();
    };

    const int tile0 = blockIdx.x * A_TPB;
    stage(tile0, 0);
    cp_wait_all();
    __syncthreads();

    for (int it = 0; it < A_TPB; it++) {
        const int buf = it & 1;
        if (it + 1 < A_TPB) stage(tile0 + it + 1, buf ^ 1);
        else cp_commit();

        const size_t bt0 = (size_t)(tile0 + it) * A_TILE;
        const float* my_half = &xs[buf][0] + kh * (A_HALF + 4);

        for (int r = 0; r < A_TILE; r += 2) {
            unsigned long long a0 = 0ull, a1 = 0ull, b0 = 0ull, b1 = 0ull;
            const ulonglong2* xr0 = (const ulonglong2*)(my_half + r * 32);
            const ulonglong2* xr1 = (const ulonglong2*)(my_half + (r + 1) * 32);
#pragma unroll
            for (int k = 0; k < 8; k++) {
                ulonglong2 v0 = xr0[k];
                ulonglong2 v1 = xr1[k];
                FMA_F32X2(a0, v0.x, w2[2 * k + 0], a0);
                FMA_F32X2(a1, v0.y, w2[2 * k + 1], a1);
                FMA_F32X2(b0, v1.x, w2[2 * k + 0], b0);
                FMA_F32X2(b1, v1.y, w2[2 * k + 1], b1);
            }
            float s0, s1, s2, s3, t0, t1, t2, t3;
            unpack2(a0, s0, s1); unpack2(a1, s2, s3);
            unpack2(b0, t0, t1); unpack2(b1, t2, t3);
            float sa = (s0 + s1) + (s2 + s3);
            float sb = (t0 + t1) + (t2 + t3);
            sa += __shfl_xor_sync(0xffffffffu, sa, 1);   // combine K-halves
            sb += __shfl_xor_sync(0xffffffffu, sb, 1);
            if (kh == 0) {
                g_xg[(bt0 + r) * GG + g] = sa + bias;
                g_xg[(bt0 + r + 1) * GG + g] = sb + bias;
            }
        }
        cp_wait_all();
        __syncthreads();
    }
}

// ---------------------------------------------------------------------------
// Kernel B: GRU recurrence on tensor cores (mma.sync bf16, 3-product split).
// 64 blocks x 16 batch rows; 512 threads = 16 warps, each owns 24 gate cols.
// W_hi fragments in registers; W_lo, h_hi, h_lo in smem (rows padded to 136
// bf16 -> fragment loads are bank-conflict-free: bank = 4*gid + tig).
// Per step: 8 k-tiles x 3 n-tiles x 3 MMAs; gate math on smem hg tile.
// ---------------------------------------------------------------------------
#define GM 16                    // batch rows per block
#define G_BLOCKS (BB / GM)       // 64
#define G_THREADS 512            // 16 warps
#define NSLICE 24                // gate cols per warp (16*24 = 384)
#define HP 136                   // padded bf16 row stride (h, W_lo)
#define HGS 388                  // padded f32 row stride (hg)

// dynamic smem layout (bytes, all 16-aligned)
#define OFF_WLO 0
#define SZ_WLO  (GG * HP * 2)              // 104448
#define OFF_HHI (OFF_WLO + SZ_WLO)
#define SZ_HB   (GM * HP * 2)              // 4352
#define OFF_HLO (OFF_HHI + SZ_HB)
#define OFF_HF  (OFF_HLO + SZ_HB)
#define SZ_HF   (GM * HH * 4)              // 8192
#define OFF_HG  (OFF_HF + SZ_HF)
#define SZ_HG   (GM * HGS * 4)             // 24832
#define OFF_XG  (OFF_HG + SZ_HG)
#define SZ_XG   (2 * GM * GG * 4)          // 49152
#define OFF_BS  (OFF_XG + SZ_XG)
#define SZ_BS   (GG * 4)
#define G_SMEM  (OFF_BS + SZ_BS)           // 196864 B

extern __shared__ __align__(16) char g_dsmem[];

__global__ __launch_bounds__(G_THREADS, 1) void gru_mma_kernel(
    const float* __restrict__ W_hh,
    const float* __restrict__ b_hh)
{
    __nv_bfloat16* Wlo = (__nv_bfloat16*)(g_dsmem + OFF_WLO);
    __nv_bfloat16* Hhi = (__nv_bfloat16*)(g_dsmem + OFF_HHI);
    __nv_bfloat16* Hlo = (__nv_bfloat16*)(g_dsmem + OFF_HLO);
    float* Hf = (float*)(g_dsmem + OFF_HF);
    float* HG = (float*)(g_dsmem + OFF_HG);
    float* XG = (float*)(g_dsmem + OFF_XG);
    float* BS = (float*)(g_dsmem + OFF_BS);

    const int tid = threadIdx.x;
    const int warp = tid >> 5;
    const int lane = tid & 31;
    const int gid = lane >> 2;               // 0..7
    const int tig = lane & 3;                // 0..3
    const int n0 = warp * NSLICE;
    const int row0 = blockIdx.x * GM;

    // --- one-time init: W_lo, biases, h=0 ---
    for (int i = tid; i < GG * HH; i += G_THREADS) {
        int n = i >> 7, k = i & 127;          // i = n*128 + k
        float w = W_hh[i];
        __nv_bfloat16 hi = __float2bfloat16(w);
        Wlo[n * HP + k] = __float2bfloat16(w - __bfloat162float(hi));
    }
    for (int i = tid; i < GG; i += G_THREADS) BS[i] = b_hh[i];
    {
        __nv_bfloat16 z = __float2bfloat16(0.f);
        for (int i = tid; i < GM * HP; i += G_THREADS) { Hhi[i] = z; Hlo[i] = z; }
        for (int i = tid; i < GM * HH; i += G_THREADS) Hf[i] = 0.f;
    }

    // --- stationary W_hi fragments in registers (3 n-tiles x 8 k-tiles) ---
    unsigned bhi[3][8][2];
#pragma unroll
    for (int nt = 0; nt < 3; nt++) {
#pragma unroll
        for (int kt = 0; kt < 8; kt++) {
            const float* wr = W_hh + (size_t)(n0 + nt * 8 + gid) * HH + kt * 16 + 2 * tig;
            bhi[nt][kt][0] = pack_bf16(wr[0], wr[1]);
            bhi[nt][kt][1] = pack_bf16(wr[8], wr[9]);
        }
    }

    const unsigned xg_base = (unsigned)__cvta_generic_to_shared(XG);
    auto stage_xg = [&](int t, int buf) {
        if (t < TT) {
            for (int c = tid; c < GM * GG / 4; c += G_THREADS) {
                int r = c / (GG / 4);
                int off = c % (GG / 4);
                const char* src =
                    (const char*)(g_xg + ((size_t)(row0 + r) * TT + t) * GG) + off * 16;
                cp_async16(xg_base + (unsigned)(buf * GM * GG + r * GG) * 4u + off * 16u, src);
            }
        }
        cp_commit();
    };

    stage_xg(0, 0);
    cp_wait_all();
    __syncthreads();

    const int jj = tid & 127;                // gate-phase column
    const int rb = tid >> 7;                 // gate-phase row base 0..3

    for (int t = 0; t < TT; t++) {
        const int buf = t & 1;
        stage_xg(t + 1, buf ^ 1);            // prefetch next step

        // --- MMA phase: hg = h @ W^T via 3-product bf16 split ---
        float acc[3][4];
#pragma unroll
        for (int nt = 0; nt < 3; nt++)
#pragma unroll
            for (int i = 0; i < 4; i++) acc[nt][i] = 0.f;

#pragma unroll
        for (int kt = 0; kt < 8; kt++) {
            const int col = kt * 16 + 2 * tig;
            unsigned ah[4], al[4];
            ah[0] = *(const unsigned*)(Hhi + gid * HP + col);
            ah[1] = *(const unsigned*)(Hhi + (gid + 8) * HP + col);
            ah[2] = *(const unsigned*)(Hhi + gid * HP + col + 8);
            ah[3] = *(const unsigned*)(Hhi + (gid + 8) * HP + col + 8);
            al[0] = *(const unsigned*)(Hlo + gid * HP + col);
            al[1] = *(const unsigned*)(Hlo + (gid + 8) * HP + col);
            al[2] = *(const unsigned*)(Hlo + gid * HP + col + 8);
            al[3] = *(const unsigned*)(Hlo + (gid + 8) * HP + col + 8);
#pragma unroll
            for (int nt = 0; nt < 3; nt++) {
                mma_bf16(acc[nt], ah, bhi[nt][kt]);   // hi * hi
                mma_bf16(acc[nt], al, bhi[nt][kt]);   // lo * hi
                unsigned bl[2];
                const __nv_bfloat16* wl = Wlo + (size_t)(n0 + nt * 8 + gid) * HP + col;
                bl[0] = *(const unsigned*)wl;
                bl[1] = *(const unsigned*)(wl + 8);
                mma_bf16(acc[nt], ah, bl);            // hi * lo
            }
        }

        // store C fragments to hg tile
#pragma unroll
        for (int nt = 0; nt < 3; nt++) {
            const int ccol = n0 + nt * 8 + 2 * tig;
            *(float2*)(HG + gid * HGS + ccol) = make_float2(acc[nt][0], acc[nt][1]);
            *(float2*)(HG + (gid + 8) * HGS + ccol) = make_float2(acc[nt][2], acc[nt][3]);
        }
        __syncthreads();

        // --- gate phase: each thread owns 4 (r, j) cells ---
        {
            const float* xg = XG + buf * GM * GG;
#pragma unroll
            for (int p = 0; p < 4; p++) {
                const int r = rb + p * 4;
                float pr = HG[r * HGS + jj] + xg[r * GG + jj] + BS[jj];
                float pz = HG[r * HGS + 128 + jj] + xg[r * GG + 128 + jj] + BS[128 + jj];
                float pn = HG[r * HGS + 256 + jj] + BS[256 + jj];
                float rr = sigmoid_fast(pr);
                float zz = sigmoid_fast(pz);
                float nn = tanh_fast(xg[r * GG + 256 + jj] + rr * pn);
                float h = (1.f - zz) * nn + zz * Hf[r * HH + jj];
                Hf[r * HH + jj] = h;
                __nv_bfloat16 hi = __float2bfloat16(h);
                Hhi[r * HP + jj] = hi;
                Hlo[r * HP + jj] = __float2bfloat16(h - __bfloat162float(hi));
            }
        }
        cp_wait_all();        // next xg buffer landed (per-thread) ...
        __syncthreads();      // ... h + xg visible block-wide
    }

    // emit final hidden state
    for (int i = tid; i < GM * HH; i += G_THREADS) {
        int r = i >> 7, j = i & 127;
        g_hT[(size_t)(row0 + r) * HH + j] = Hf[r * HH + j];
    }
}

// ---------------------------------------------------------------------------
// Kernel C: out[b] = W2 . relu(hT[b] @ W1^T + b1) + b2. One warp per row.
// ---------------------------------------------------------------------------
__global__ void head_kernel(
    const float* __restrict__ W1,
    const float* __restrict__ b1,
    const float* __restrict__ W2,
    const float* __restrict__ b2,
    float* __restrict__ out)
{
    const int b = blockIdx.x;
    const int j = threadIdx.x;                       // 0..31
    const float* h = g_hT + (size_t)b * HH;

    float acc = 0.f;
#pragma unroll
    for (int k = 0; k < HH; k++)
        acc = fmaf(h[k], W1[j * HH + k], acc);

    float hid = fmaxf(acc + b1[j], 0.f);
    float v = hid * W2[j];
#pragma unroll
    for (int off = 16; off; off >>= 1)
        v += __shfl_xor_sync(0xffffffffu, v, off);
    if (j == 0) out[b] = v + b2[0];
}

// ---------------------------------------------------------------------------
extern "C" void kernel_launch(void* const* d_in, const int* in_sizes, int n_in,
                              void* d_out, int out_size)
{
    const float* x    = (const float*)d_in[0];
    const float* W_ih = (const float*)d_in[1];
    const float* W_hh = (const float*)d_in[2];
    const float* b_ih = (const float*)d_in[3];
    const float* b_hh = (const float*)d_in[4];
    const float* W1   = (const float*)d_in[5];
    const float* b1   = (const float*)d_in[6];
    const float* W2   = (const float*)d_in[7];
    const float* b2   = (const float*)d_in[8];
    float* out        = (float*)d_out;

    cudaFuncSetAttribute(gru_mma_kernel,
                         cudaFuncAttributeMaxDynamicSharedMemorySize, G_SMEM);

    xg_kernel<<<A_BLOCKS, A_THREADS>>>(x, W_ih, b_ih);
    gru_mma_kernel<<<G_BLOCKS, G_THREADS, G_SMEM>>>(W_hh, b_hh);
    head_kernel<<<BB, 32>>>(W1, b1, W2, b2, out);
}

// round 10
// speedup vs baseline: 2.5317x; 1.3355x over previous
#include <cuda_runtime.h>
#include <cuda_bf16.h>
#include <math.h>

// Problem dims
#define BB 1024
#define TT 512
#define FF 64
#define HH 128
#define GG 384   // 3*H, gate order (r, z, n)

__device__ __forceinline__ float sigmoid_fast(float x) {
    return __fdividef(1.f, 1.f + __expf(-x));
}
__device__ __forceinline__ float tanh_fast(float x) {
    return 1.f - __fdividef(2.f, __expf(2.f * x) + 1.f);
}

// cp.async helpers (16B)
__device__ __forceinline__ void cp_async16(unsigned int smem_addr, const void* gptr) {
    asm volatile("cp.async.cg.shared.global [%0], [%1], 16;" :: "r"(smem_addr), "l"(gptr));
}
__device__ __forceinline__ void cp_commit() {
    asm volatile("cp.async.commit_group;");
}
__device__ __forceinline__ void cp_wait_all() {
    asm volatile("cp.async.wait_group 0;" ::: "memory");
}

// bf16 mma m16n8k16 row.col, f32 accumulate
__device__ __forceinline__ void mma_bf16(float* c, const unsigned* a, const unsigned* b) {
    asm volatile(
        "mma.sync.aligned.m16n8k16.row.col.f32.bf16.bf16.f32 "
        "{%0,%1,%2,%3}, {%4,%5,%6,%7}, {%8,%9}, {%0,%1,%2,%3};"
        : "+f"(c[0]), "+f"(c[1]), "+f"(c[2]), "+f"(c[3])
        : "r"(a[0]), "r"(a[1]), "r"(a[2]), "r"(a[3]), "r"(b[0]), "r"(b[1]));
}

__device__ __forceinline__ unsigned pack_bf16(float f0, float f1) {
    unsigned short u0 = __bfloat16_as_ushort(__float2bfloat16(f0));
    unsigned short u1 = __bfloat16_as_ushort(__float2bfloat16(f1));
    return (unsigned)u0 | ((unsigned)u1 << 16);
}

// Scratch (allocation-free rule: __device__ globals)
__device__ float g_xg[(size_t)BB * TT * GG];  // [B*T, 3H] input-side pre-acts (includes b_ih)
__device__ float g_hT[BB * HH];               // final hidden state

extern __shared__ __align__(16) char g_dsmem[];

#define HGS 388                  // padded f32 row stride (frag-store tiles)

// ---------------------------------------------------------------------------
// Kernel A: xg = x @ W_ih^T + b_ih on tensor cores (3-product bf16 split).
// 148 persistent blocks x 512 threads (16 warps, nslice 24), grid-stride over
// 32768 bt-tiles of 16 rows. W_hi frags stationary in regs; W_lo, x hi/lo in
// smem (stride 72 bf16 -> bank 4*gid+tig, conflict-free). K=64 -> 4 k-tiles.
// ---------------------------------------------------------------------------
#define XNT (BB * TT / 16)       // 32768 tiles
#define X_THREADS 512
#define X_BLOCKS 148
#define WPAD 72                  // padded bf16 K-stride

// dynamic smem layout (bytes, 16-aligned)
#define X_OFF_WLO 0
#define X_SZ_WLO  (GG * WPAD * 2)           // 55296
#define X_OFF_XF  (X_OFF_WLO + X_SZ_WLO)
#define X_SZ_XF   (2 * 16 * FF * 4)         // 8192
#define X_OFF_XHI (X_OFF_XF + X_SZ_XF)
#define X_SZ_XB   (2 * 16 * WPAD * 2)       // 4608
#define X_OFF_XLO (X_OFF_XHI + X_SZ_XB)
#define X_OFF_HG  (X_OFF_XLO + X_SZ_XB)
#define X_SZ_HG   (16 * HGS * 4)            // 24832
#define X_OFF_BS  (X_OFF_HG + X_SZ_HG)
#define X_SZ_BS   (GG * 4)
#define X_SMEM    (X_OFF_BS + X_SZ_BS)      // 99072 B

__global__ __launch_bounds__(X_THREADS, 1) void xg_mma_kernel(
    const float* __restrict__ x,
    const float* __restrict__ W_ih,
    const float* __restrict__ b_ih)
{
    __nv_bfloat16* Wlo = (__nv_bfloat16*)(g_dsmem + X_OFF_WLO);
    float* Xf = (float*)(g_dsmem + X_OFF_XF);                 // [2][16][64]
    __nv_bfloat16* Xhi = (__nv_bfloat16*)(g_dsmem + X_OFF_XHI);  // [2][16][WPAD]
    __nv_bfloat16* Xlo = (__nv_bfloat16*)(g_dsmem + X_OFF_XLO);
    float* HG = (float*)(g_dsmem + X_OFF_HG);                 // [16][HGS]
    float* BS = (float*)(g_dsmem + X_OFF_BS);

    const int tid = threadIdx.x;
    const int warp = tid >> 5;
    const int lane = tid & 31;
    const int gid = lane >> 2;
    const int tig = lane & 3;
    const int n0 = warp * 24;

    // one-time: W_lo split, biases
    for (int i = tid; i < GG * FF; i += X_THREADS) {
        int n = i >> 6, k = i & 63;
        float w = W_ih[i];
        __nv_bfloat16 hi = __float2bfloat16(w);
        Wlo[n * WPAD + k] = __float2bfloat16(w - __bfloat162float(hi));
    }
    for (int i = tid; i < GG; i += X_THREADS) BS[i] = b_ih[i];

    // stationary W_hi fragments (3 n-tiles x 4 k-tiles)
    unsigned bhi[3][4][2];
#pragma unroll
    for (int nt = 0; nt < 3; nt++)
#pragma unroll
        for (int kt = 0; kt < 4; kt++) {
            const float* wr = W_ih + (size_t)(n0 + nt * 8 + gid) * FF + kt * 16 + 2 * tig;
            bhi[nt][kt][0] = pack_bf16(wr[0], wr[1]);
            bhi[nt][kt][1] = pack_bf16(wr[8], wr[9]);
        }

    const unsigned xf_base = (unsigned)__cvta_generic_to_shared(Xf);
    auto stage = [&](int tile, int buf) {
        if (tile < XNT && tid < 256)
            cp_async16(xf_base + (unsigned)buf * 4096u + (unsigned)tid * 16u,
                       (const char*)x + (size_t)tile * 4096 + (size_t)tid * 16);
        cp_commit();
    };

    stage(blockIdx.x, 0);
    cp_wait_all();
    __syncthreads();

    int it = 0;
    for (int tile = blockIdx.x; tile < XNT; tile += gridDim.x, it++) {
        const int buf = it & 1;
        stage(tile + gridDim.x, buf ^ 1);

        // convert x tile fp32 -> bf16 hi/lo
        for (int i = tid; i < 16 * FF; i += X_THREADS) {
            int r = i >> 6, c = i & 63;
            float v = Xf[buf * 1024 + i];
            __nv_bfloat16 hi = __float2bfloat16(v);
            Xhi[buf * 16 * WPAD + r * WPAD + c] = hi;
            Xlo[buf * 16 * WPAD + r * WPAD + c] =
                __float2bfloat16(v - __bfloat162float(hi));
        }
        __syncthreads();

        // MMA: 3-product split over 4 k-tiles
        float acc[3][4];
#pragma unroll
        for (int nt = 0; nt < 3; nt++)
#pragma unroll
            for (int i = 0; i < 4; i++) acc[nt][i] = 0.f;

        const __nv_bfloat16* XH = Xhi + buf * 16 * WPAD;
        const __nv_bfloat16* XL = Xlo + buf * 16 * WPAD;
#pragma unroll
        for (int kt = 0; kt < 4; kt++) {
            const int col = kt * 16 + 2 * tig;
            unsigned ah[4], al[4];
            ah[0] = *(const unsigned*)(XH + gid * WPAD + col);
            ah[1] = *(const unsigned*)(XH + (gid + 8) * WPAD + col);
            ah[2] = *(const unsigned*)(XH + gid * WPAD + col + 8);
            ah[3] = *(const unsigned*)(XH + (gid + 8) * WPAD + col + 8);
            al[0] = *(const unsigned*)(XL + gid * WPAD + col);
            al[1] = *(const unsigned*)(XL + (gid + 8) * WPAD + col);
            al[2] = *(const unsigned*)(XL + gid * WPAD + col + 8);
            al[3] = *(const unsigned*)(XL + (gid + 8) * WPAD + col + 8);
#pragma unroll
            for (int nt = 0; nt < 3; nt++) {
                mma_bf16(acc[nt], ah, bhi[nt][kt]);   // hi * hi
                mma_bf16(acc[nt], al, bhi[nt][kt]);   // lo * hi
                unsigned bl[2];
                const __nv_bfloat16* wl = Wlo + (size_t)(n0 + nt * 8 + gid) * WPAD + col;
                bl[0] = *(const unsigned*)wl;
                bl[1] = *(const unsigned*)(wl + 8);
                mma_bf16(acc[nt], ah, bl);            // hi * lo
            }
        }

        // frag store to HG
#pragma unroll
        for (int nt = 0; nt < 3; nt++) {
            const int ccol = n0 + nt * 8 + 2 * tig;
            *(float2*)(HG + gid * HGS + ccol) = make_float2(acc[nt][0], acc[nt][1]);
            *(float2*)(HG + (gid + 8) * HGS + ccol) = make_float2(acc[nt][2], acc[nt][3]);
        }
        __syncthreads();

        // coalesced write-out with bias (16x384 contiguous in g_xg)
        {
            float* dst = g_xg + (size_t)tile * 16 * GG;
#pragma unroll
            for (int p = 0; p < 3; p++) {
                int f = tid + p * X_THREADS;          // 0..1535 float4s
                int col = (f * 4) % GG;
                int row = (f * 4) / GG;
                float4 v = *(const float4*)(HG + row * HGS + col);
                float4 b = *(const float4*)(BS + col);
                v.x += b.x; v.y += b.y; v.z += b.z; v.w += b.w;
                *(float4*)(dst + (size_t)f * 4) = v;
            }
        }
        cp_wait_all();
        __syncthreads();
    }
}

// ---------------------------------------------------------------------------
// Kernel B: GRU recurrence on tensor cores (unchanged from passing R8 build).
// ---------------------------------------------------------------------------
#define GM 16                    // batch rows per block
#define G_BLOCKS (BB / GM)       // 64
#define G_THREADS 512            // 16 warps
#define NSLICE 24                // gate cols per warp
#define HP 136                   // padded bf16 row stride (h, W_lo)

#define OFF_WLO 0
#define SZ_WLO  (GG * HP * 2)              // 104448
#define OFF_HHI (OFF_WLO + SZ_WLO)
#define SZ_HB   (GM * HP * 2)              // 4352
#define OFF_HLO (OFF_HHI + SZ_HB)
#define OFF_HF  (OFF_HLO + SZ_HB)
#define SZ_HF   (GM * HH * 4)              // 8192
#define OFF_HG  (OFF_HF + SZ_HF)
#define SZ_HG   (GM * HGS * 4)             // 24832
#define OFF_XG  (OFF_HG + SZ_HG)
#define SZ_XG   (2 * GM * GG * 4)          // 49152
#define OFF_BS  (OFF_XG + SZ_XG)
#define SZ_BS   (GG * 4)
#define G_SMEM  (OFF_BS + SZ_BS)           // 196864 B

__global__ __launch_bounds__(G_THREADS, 1) void gru_mma_kernel(
    const float* __restrict__ W_hh,
    const float* __restrict__ b_hh)
{
    __nv_bfloat16* Wlo = (__nv_bfloat16*)(g_dsmem + OFF_WLO);
    __nv_bfloat16* Hhi = (__nv_bfloat16*)(g_dsmem + OFF_HHI);
    __nv_bfloat16* Hlo = (__nv_bfloat16*)(g_dsmem + OFF_HLO);
    float* Hf = (float*)(g_dsmem + OFF_HF);
    float* HG = (float*)(g_dsmem + OFF_HG);
    float* XG = (float*)(g_dsmem + OFF_XG);
    float* BS = (float*)(g_dsmem + OFF_BS);

    const int tid = threadIdx.x;
    const int warp = tid >> 5;
    const int lane = tid & 31;
    const int gid = lane >> 2;
    const int tig = lane & 3;
    const int n0 = warp * NSLICE;
    const int row0 = blockIdx.x * GM;

    for (int i = tid; i < GG * HH; i += G_THREADS) {
        int n = i >> 7, k = i & 127;
        float w = W_hh[i];
        __nv_bfloat16 hi = __float2bfloat16(w);
        Wlo[n * HP + k] = __float2bfloat16(w - __bfloat162float(hi));
    }
    for (int i = tid; i < GG; i += G_THREADS) BS[i] = b_hh[i];
    {
        __nv_bfloat16 z = __float2bfloat16(0.f);
        for (int i = tid; i < GM * HP; i += G_THREADS) { Hhi[i] = z; Hlo[i] = z; }
        for (int i = tid; i < GM * HH; i += G_THREADS) Hf[i] = 0.f;
    }

    unsigned bhi[3][8][2];
#pragma unroll
    for (int nt = 0; nt < 3; nt++)
#pragma unroll
        for (int kt = 0; kt < 8; kt++) {
            const float* wr = W_hh + (size_t)(n0 + nt * 8 + gid) * HH + kt * 16 + 2 * tig;
            bhi[nt][kt][0] = pack_bf16(wr[0], wr[1]);
            bhi[nt][kt][1] = pack_bf16(wr[8], wr[9]);
        }

    const unsigned xg_base = (unsigned)__cvta_generic_to_shared(XG);
    auto stage_xg = [&](int t, int buf) {
        if (t < TT) {
            for (int c = tid; c < GM * GG / 4; c += G_THREADS) {
                int r = c / (GG / 4);
                int off = c % (GG / 4);
                const char* src =
                    (const char*)(g_xg + ((size_t)(row0 + r) * TT + t) * GG) + off * 16;
                cp_async16(xg_base + (unsigned)(buf * GM * GG + r * GG) * 4u + off * 16u, src);
            }
        }
        cp_commit();
    };

    stage_xg(0, 0);
    cp_wait_all();
    __syncthreads();

    const int jj = tid & 127;
    const int rb = tid >> 7;

    for (int t = 0; t < TT; t++) {
        const int buf = t & 1;
        stage_xg(t + 1, buf ^ 1);

        float acc[3][4];
#pragma unroll
        for (int nt = 0; nt < 3; nt++)
#pragma unroll
            for (int i = 0; i < 4; i++) acc[nt][i] = 0.f;

#pragma unroll
        for (int kt = 0; kt < 8; kt++) {
            const int col = kt * 16 + 2 * tig;
            unsigned ah[4], al[4];
            ah[0] = *(const unsigned*)(Hhi + gid * HP + col);
            ah[1] = *(const unsigned*)(Hhi + (gid + 8) * HP + col);
            ah[2] = *(const unsigned*)(Hhi + gid * HP + col + 8);
            ah[3] = *(const unsigned*)(Hhi + (gid + 8) * HP + col + 8);
            al[0] = *(const unsigned*)(Hlo + gid * HP + col);
            al[1] = *(const unsigned*)(Hlo + (gid + 8) * HP + col);
            al[2] = *(const unsigned*)(Hlo + gid * HP + col + 8);
            al[3] = *(const unsigned*)(Hlo + (gid + 8) * HP + col + 8);
#pragma unroll
            for (int nt = 0; nt < 3; nt++) {
                mma_bf16(acc[nt], ah, bhi[nt][kt]);
                mma_bf16(acc[nt], al, bhi[nt][kt]);
                unsigned bl[2];
                const __nv_bfloat16* wl = Wlo + (size_t)(n0 + nt * 8 + gid) * HP + col;
                bl[0] = *(const unsigned*)wl;
                bl[1] = *(const unsigned*)(wl + 8);
                mma_bf16(acc[nt], ah, bl);
            }
        }

#pragma unroll
        for (int nt = 0; nt < 3; nt++) {
            const int ccol = n0 + nt * 8 + 2 * tig;
            *(float2*)(HG + gid * HGS + ccol) = make_float2(acc[nt][0], acc[nt][1]);
            *(float2*)(HG + (gid + 8) * HGS + ccol) = make_float2(acc[nt][2], acc[nt][3]);
        }
        __syncthreads();

        {
            const float* xg = XG + buf * GM * GG;
#pragma unroll
            for (int p = 0; p < 4; p++) {
                const int r = rb + p * 4;
                float pr = HG[r * HGS + jj] + xg[r * GG + jj] + BS[jj];
                float pz = HG[r * HGS + 128 + jj] + xg[r * GG + 128 + jj] + BS[128 + jj];
                float pn = HG[r * HGS + 256 + jj] + BS[256 + jj];
                float rr = sigmoid_fast(pr);
                float zz = sigmoid_fast(pz);
                float nn = tanh_fast(xg[r * GG + 256 + jj] + rr * pn);
                float h = (1.f - zz) * nn + zz * Hf[r * HH + jj];
                Hf[r * HH + jj] = h;
                __nv_bfloat16 hi = __float2bfloat16(h);
                Hhi[r * HP + jj] = hi;
                Hlo[r * HP + jj] = __float2bfloat16(h - __bfloat162float(hi));
            }
        }
        cp_wait_all();
        __syncthreads();
    }

    for (int i = tid; i < GM * HH; i += G_THREADS) {
        int r = i >> 7, j = i & 127;
        g_hT[(size_t)(row0 + r) * HH + j] = Hf[r * HH + j];
    }
}

// ---------------------------------------------------------------------------
// Kernel C: out[b] = W2 . relu(hT[b] @ W1^T + b1) + b2. One warp per row.
// ---------------------------------------------------------------------------
__global__ void head_kernel(
    const float* __restrict__ W1,
    const float* __restrict__ b1,
    const float* __restrict__ W2,
    const float* __restrict__ b2,
    float* __restrict__ out)
{
    const int b = blockIdx.x;
    const int j = threadIdx.x;
    const float* h = g_hT + (size_t)b * HH;

    float acc = 0.f;
#pragma unroll
    for (int k = 0; k < HH; k++)
        acc = fmaf(h[k], W1[j * HH + k], acc);

    float hid = fmaxf(acc + b1[j], 0.f);
    float v = hid * W2[j];
#pragma unroll
    for (int off = 16; off; off >>= 1)
        v += __shfl_xor_sync(0xffffffffu, v, off);
    if (j == 0) out[b] = v + b2[0];
}

// ---------------------------------------------------------------------------
extern "C" void kernel_launch(void* const* d_in, const int* in_sizes, int n_in,
                              void* d_out, int out_size)
{
    const float* x    = (const float*)d_in[0];
    const float* W_ih = (const float*)d_in[1];
    const float* W_hh = (const float*)d_in[2];
    const float* b_ih = (const float*)d_in[3];
    const float* b_hh = (const float*)d_in[4];
    const float* W1   = (const float*)d_in[5];
    const float* b1   = (const float*)d_in[6];
    const float* W2   = (const float*)d_in[7];
    const float* b2   = (const float*)d_in[8];
    float* out        = (float*)d_out;

    cudaFuncSetAttribute(xg_mma_kernel,
                         cudaFuncAttributeMaxDynamicSharedMemorySize, X_SMEM);
    cudaFuncSetAttribute(gru_mma_kernel,
                         cudaFuncAttributeMaxDynamicSharedMemorySize, G_SMEM);

    xg_mma_kernel<<<X_BLOCKS, X_THREADS, X_SMEM>>>(x, W_ih, b_ih);
    gru_mma_kernel<<<G_BLOCKS, G_THREADS, G_SMEM>>>(W_hh, b_hh);
    head_kernel<<<BB, 32>>>(W1, b1, W2, b2, out);
}